// round 1
// baseline (speedup 1.0000x reference)
#include <cuda_runtime.h>
#include <math.h>

// ---------------- problem constants ----------------
#define BATCH 64
#define NTOK 197
#define NPATCH 196
#define EMBED 192
#define HEADS 3
#define HDIM 64
#define FEAT 256
#define MLPD 768
#define NCLS 1000
#define DEPTH 12
#define ROWS (BATCH*NTOK)   // 12608

// ---------------- scratch (device globals; no allocation allowed) ----------------
__device__ float g_h   [BATCH*NTOK*EMBED];
__device__ float g_xln [BATCH*NTOK*EMBED];
__device__ float g_qkv [BATCH*NTOK*3*EMBED];
__device__ float g_q   [BATCH*HEADS*NTOK*HDIM];
__device__ float g_k   [BATCH*HEADS*NTOK*HDIM];
__device__ float g_v   [BATCH*HEADS*NTOK*HDIM];
__device__ float g_pq  [BATCH*HEADS*NTOK*FEAT];
__device__ float g_pk  [BATCH*HEADS*NTOK*FEAT];
__device__ float g_ks  [BATCH*HEADS*FEAT];
__device__ float g_dv  [BATCH*HEADS*NTOK];
__device__ float g_attn[BATCH*HEADS*NTOK*NTOK];
__device__ float g_ao  [BATCH*NTOK*EMBED];
__device__ float g_mlp [BATCH*NTOK*MLPD];
__device__ float g_pool[BATCH*EMBED];
__device__ float g_cls [BATCH*EMBED];

// ---------------- helpers ----------------
// block-wide sum for blockDim.x == 192 (6 warps)
__device__ __forceinline__ float blockSum192(float v, float* sm) {
    #pragma unroll
    for (int o = 16; o > 0; o >>= 1) v += __shfl_down_sync(0xffffffffu, v, o);
    if ((threadIdx.x & 31) == 0) sm[threadIdx.x >> 5] = v;
    __syncthreads();
    float tot = 0.f;
    #pragma unroll
    for (int i = 0; i < 6; i++) tot += sm[i];
    __syncthreads();
    return tot;
}

// ---------------- generic register-tiled GEMM ----------------
// C[M,N] = A[M,K] @ B  (+bias, +gelu, +residual)
// TB:   B stored row-major [N,K] (i.e. compute A @ B^T)
// DINV: performer attn@v epilogue: z=(b*3+h); scale row by dinv, scatter to
//       C[(b*NTOK+row)*EMBED + h*HDIM + col]
#define BM 64
#define BN 64
#define BKK 16

template<bool GELU, bool TB, bool RESID, bool DINV>
__global__ __launch_bounds__(256)
void gemm_k(const float* __restrict__ A, const float* __restrict__ Bm,
            const float* __restrict__ bias, const float* __restrict__ res,
            const float* __restrict__ dinv, float* __restrict__ C,
            int M, int N, int K, long sA, long sB, long sC)
{
    __shared__ float As[BKK][BM + 4];
    __shared__ float Bs[BKK][BN + 4];
    int z = blockIdx.z;
    const float* Ab = A + (long)z * sA;
    const float* Bb = Bm + (long)z * sB;
    int mBase = blockIdx.y * BM;
    int nBase = blockIdx.x * BN;
    int tid = threadIdx.x;
    int tx = tid & 15, ty = tid >> 4;

    float acc[4][4];
    #pragma unroll
    for (int i = 0; i < 4; i++)
        #pragma unroll
        for (int j = 0; j < 4; j++) acc[i][j] = 0.f;

    for (int k0 = 0; k0 < K; k0 += BKK) {
        {   // load A tile (transposed into As[kk][m])
            int m = tid >> 2; int kk4 = (tid & 3) * 4;
            int gm = mBase + m;
            const float* ap = Ab + (long)gm * K + k0 + kk4;
            #pragma unroll
            for (int u = 0; u < 4; u++) {
                int gk = k0 + kk4 + u;
                As[kk4 + u][m] = (gm < M && gk < K) ? ap[u] : 0.f;
            }
        }
        if (TB) {
            int n = tid >> 2; int kk4 = (tid & 3) * 4;
            int gn = nBase + n;
            const float* bp = Bb + (long)gn * K + k0 + kk4;
            #pragma unroll
            for (int u = 0; u < 4; u++) {
                int gk = k0 + kk4 + u;
                Bs[kk4 + u][n] = (gn < N && gk < K) ? bp[u] : 0.f;
            }
        } else {
            int kk = tid >> 4; int n4 = (tid & 15) * 4;
            int gk = k0 + kk;
            const float* bp = Bb + (long)gk * N + nBase + n4;
            #pragma unroll
            for (int u = 0; u < 4; u++) {
                int gn = nBase + n4 + u;
                Bs[kk][n4 + u] = (gk < K && gn < N) ? bp[u] : 0.f;
            }
        }
        __syncthreads();
        #pragma unroll
        for (int kk = 0; kk < BKK; kk++) {
            float4 a = *(const float4*)&As[kk][ty * 4];
            float4 b = *(const float4*)&Bs[kk][tx * 4];
            float av[4] = {a.x, a.y, a.z, a.w};
            float bv[4] = {b.x, b.y, b.z, b.w};
            #pragma unroll
            for (int i = 0; i < 4; i++)
                #pragma unroll
                for (int j = 0; j < 4; j++) acc[i][j] += av[i] * bv[j];
        }
        __syncthreads();
    }

    if (DINV) {
        int bb = z / 3, hh = z % 3;
        float* Cp = C + (long)bb * NTOK * EMBED + hh * HDIM;
        #pragma unroll
        for (int i = 0; i < 4; i++) {
            int row = mBase + ty * 4 + i;
            if (row >= M) continue;
            float dvv = dinv[(long)z * NTOK + row];
            #pragma unroll
            for (int j = 0; j < 4; j++) {
                int col = nBase + tx * 4 + j;
                if (col < N) Cp[(long)row * EMBED + col] = acc[i][j] * dvv;
            }
        }
    } else {
        float* Cp = C + (long)z * sC;
        #pragma unroll
        for (int i = 0; i < 4; i++) {
            int row = mBase + ty * 4 + i;
            if (row >= M) continue;
            #pragma unroll
            for (int j = 0; j < 4; j++) {
                int col = nBase + tx * 4 + j;
                if (col >= N) continue;
                float vv = acc[i][j];
                if (bias) vv += bias[col];
                if (GELU) vv = 0.5f * vv * (1.0f + erff(vv * 0.70710678118654752f));
                if (RESID) vv += res[(long)row * N + col];
                Cp[(long)row * N + col] = vv;
            }
        }
    }
}

// ---------------- LayerNorm (192 threads per row) ----------------
__global__ void ln_k(const float* __restrict__ in, long rowStride,
                     const float* __restrict__ w, const float* __restrict__ b,
                     float* __restrict__ out)
{
    __shared__ float sm[8];
    long r = blockIdx.x;
    int t = threadIdx.x;
    float v = in[r * rowStride + t];
    float mu = blockSum192(v, sm) * (1.f / EMBED);
    float d = v - mu;
    float var = blockSum192(d * d, sm) * (1.f / EMBED);
    out[r * EMBED + t] = d * rsqrtf(var + 1e-5f) * w[t] + b[t];
}

// ---------------- patch embed + LN + pos (8 patches per block) ----------------
__global__ __launch_bounds__(192)
void patch_k(const float* __restrict__ x, const float* __restrict__ w,
             const float* __restrict__ wb, const float* __restrict__ lw,
             const float* __restrict__ lb, const float* __restrict__ pos,
             float* __restrict__ h)
{
    __shared__ float px[8][768];
    __shared__ float sm[8];
    int b = blockIdx.x;
    int pbase = blockIdx.y * 8;
    int np = NPATCH - pbase; if (np > 8) np = 8;
    int tid = threadIdx.x;

    for (int j = 0; j < np; j++) {
        int p = pbase + j;
        int gy = p / 14, gx = p % 14;
        for (int t = tid; t < 768; t += 192) {
            int c = t >> 8; int rem = t & 255; int r = rem >> 4; int col = rem & 15;
            px[j][t] = x[(((long)b * 3 + c) * 224 + gy * 16 + r) * 224 + gx * 16 + col];
        }
    }
    __syncthreads();

    float acc[8];
    #pragma unroll
    for (int j = 0; j < 8; j++) acc[j] = 0.f;
    const float4* wr = (const float4*)(w + (long)tid * 768);
    for (int k4 = 0; k4 < 192; k4++) {
        float4 wv = wr[k4];
        int k = k4 * 4;
        #pragma unroll
        for (int j = 0; j < 8; j++) {
            acc[j] += wv.x * px[j][k]   + wv.y * px[j][k+1]
                    + wv.z * px[j][k+2] + wv.w * px[j][k+3];
        }
    }
    float bval = wb[tid];
    for (int j = 0; j < np; j++) {
        float v = acc[j] + bval;
        float mu  = blockSum192(v, sm) * (1.f / 192.f);
        float d = v - mu;
        float var = blockSum192(d * d, sm) * (1.f / 192.f);
        float o = d * rsqrtf(var + 1e-5f) * lw[tid] + lb[tid];
        int p = pbase + j;
        h[((long)b * NTOK + 1 + p) * EMBED + tid] = o + pos[(1 + p) * EMBED + tid];
    }
}

__global__ void cls_k(const float* __restrict__ cls, const float* __restrict__ pos,
                      float* __restrict__ h)
{
    int b = blockIdx.x; int e = threadIdx.x;
    h[(long)b * NTOK * EMBED + e] = cls[e] + pos[e];
}

// ---------------- qkv split into [B,H,N,64] ----------------
__global__ void split_k(const float* __restrict__ qkv, float* __restrict__ q,
                        float* __restrict__ k, float* __restrict__ v)
{
    long idx = (long)blockIdx.x * 256 + threadIdx.x;
    if (idx >= (long)BATCH * NTOK * 3 * EMBED) return;
    int d  = (int)(idx & 63);
    int h  = (int)((idx >> 6) % 3);
    int q3 = (int)((idx / 192) % 3);
    long bn = idx / 576;
    int n = (int)(bn % NTOK);
    long b = bn / NTOK;
    float val = qkv[idx];
    long o = ((b * 3 + h) * NTOK + n) * 64 + d;
    if (q3 == 0) q[o] = val; else if (q3 == 1) k[o] = val; else v[o] = val;
}

// ---------------- performer feature map ----------------
__global__ __launch_bounds__(256)
void fmap_k(const float* __restrict__ q, const float* __restrict__ k,
            const float* __restrict__ pm, float* __restrict__ pq, float* __restrict__ pk)
{
    __shared__ float t[64];
    __shared__ float sm[2];
    __shared__ float nrm;
    long row = blockIdx.x;
    const float* src = blockIdx.y ? k : q;
    float* dst = blockIdx.y ? pk : pq;
    int tid = threadIdx.x;
    if (tid < 64) t[tid] = src[row * 64 + tid];
    __syncthreads();
    if (tid < 64) {
        float v = t[tid]; v = v * v;
        #pragma unroll
        for (int o = 16; o > 0; o >>= 1) v += __shfl_down_sync(0xffffffffu, v, o);
        if ((tid & 31) == 0) sm[tid >> 5] = v;
    }
    __syncthreads();
    if (tid == 0) nrm = (sm[0] + sm[1]) * 0.5f;
    __syncthreads();
    float dot = 0.f;
    const float4* pr = (const float4*)(pm + (long)tid * 64);
    #pragma unroll
    for (int d4 = 0; d4 < 16; d4++) {
        float4 p4 = pr[d4];
        int d = d4 * 4;
        dot += p4.x * t[d] + p4.y * t[d+1] + p4.z * t[d+2] + p4.w * t[d+3];
    }
    dst[row * FEAT + tid] = expf(dot - nrm) * 0.35355339059327373f;
}

// ---------------- k_cumsum over tokens ----------------
__global__ void ksum_k(const float* __restrict__ pk, float* __restrict__ ks)
{
    int z = blockIdx.x; int f = threadIdx.x;
    float s = 0.f;
    for (int n = 0; n < NTOK; n++) s += pk[((long)z * NTOK + n) * FEAT + f];
    ks[(long)z * FEAT + f] = s;
}

// ---------------- D_inv ----------------
__global__ __launch_bounds__(256)
void dinv_k(const float* __restrict__ pq, const float* __restrict__ ks,
            float* __restrict__ dv)
{
    __shared__ float s[FEAT];
    int z = blockIdx.x;
    int tid = threadIdx.x;
    s[tid] = ks[(long)z * FEAT + tid];
    __syncthreads();
    int w = tid >> 5, l = tid & 31;
    int n = blockIdx.y * 8 + w;
    if (n < NTOK) {
        const float* p = pq + ((long)z * NTOK + n) * FEAT;
        float acc = 0.f;
        #pragma unroll
        for (int f = 0; f < FEAT / 32; f++) acc += p[l + f * 32] * s[l + f * 32];
        #pragma unroll
        for (int o = 16; o > 0; o >>= 1) acc += __shfl_down_sync(0xffffffffu, acc, o);
        if (l == 0) dv[(long)z * NTOK + n] = 1.f / acc;
    }
}

// ---------------- token mean pool ----------------
__global__ void pool_k(const float* __restrict__ h, float* __restrict__ pool)
{
    int b = blockIdx.x; int e = threadIdx.x;
    float s = 0.f;
    for (int n = 0; n < NTOK; n++) s += h[((long)b * NTOK + n) * EMBED + e];
    pool[b * EMBED + e] = s * (1.f / 197.f);
}

// ---------------- host launch ----------------
extern "C" void kernel_launch(void* const* d_in, const int* in_sizes, int n_in,
                              void* d_out, int out_size)
{
    const float* x            = (const float*)d_in[0];
    const float* patch_w      = (const float*)d_in[1];
    const float* patch_b      = (const float*)d_in[2];
    const float* pe_norm_w    = (const float*)d_in[3];
    const float* pe_norm_b    = (const float*)d_in[4];
    const float* cls_token    = (const float*)d_in[5];
    const float* pos_embed    = (const float*)d_in[6];
    const float* norm1_w      = (const float*)d_in[7];
    const float* norm1_b      = (const float*)d_in[8];
    const float* qkv_w        = (const float*)d_in[9];
    const float* qkv_b        = (const float*)d_in[10];
    const float* proj_mat     = (const float*)d_in[11];
    const float* attn_proj_w  = (const float*)d_in[12];
    const float* attn_proj_b  = (const float*)d_in[13];
    const float* norm2_w      = (const float*)d_in[14];
    const float* norm2_b      = (const float*)d_in[15];
    const float* fc1_w        = (const float*)d_in[16];
    const float* fc1_b        = (const float*)d_in[17];
    const float* fc2_w        = (const float*)d_in[18];
    const float* fc2_b        = (const float*)d_in[19];
    const float* exit_w       = (const float*)d_in[20];
    const float* exit_b       = (const float*)d_in[21];
    const float* final_norm_w = (const float*)d_in[22];
    const float* final_norm_b = (const float*)d_in[23];
    const float* head_w       = (const float*)d_in[24];
    const float* head_b       = (const float*)d_in[25];
    float* out = (float*)d_out;

    float *h, *xln, *qkv, *q, *k, *v, *pq, *pk, *ks, *dv, *attn, *ao, *mlp, *pool, *cls;
    cudaGetSymbolAddress((void**)&h,    g_h);
    cudaGetSymbolAddress((void**)&xln,  g_xln);
    cudaGetSymbolAddress((void**)&qkv,  g_qkv);
    cudaGetSymbolAddress((void**)&q,    g_q);
    cudaGetSymbolAddress((void**)&k,    g_k);
    cudaGetSymbolAddress((void**)&v,    g_v);
    cudaGetSymbolAddress((void**)&pq,   g_pq);
    cudaGetSymbolAddress((void**)&pk,   g_pk);
    cudaGetSymbolAddress((void**)&ks,   g_ks);
    cudaGetSymbolAddress((void**)&dv,   g_dv);
    cudaGetSymbolAddress((void**)&attn, g_attn);
    cudaGetSymbolAddress((void**)&ao,   g_ao);
    cudaGetSymbolAddress((void**)&mlp,  g_mlp);
    cudaGetSymbolAddress((void**)&pool, g_pool);
    cudaGetSymbolAddress((void**)&cls,  g_cls);

    // embed
    cls_k<<<BATCH, EMBED>>>(cls_token, pos_embed, h);
    patch_k<<<dim3(BATCH, 25), 192>>>(x, patch_w, patch_b, pe_norm_w, pe_norm_b,
                                      pos_embed, h);

    for (int i = 0; i < DEPTH; i++) {
        // LN1
        ln_k<<<ROWS, EMBED>>>(h, EMBED, norm1_w + i * EMBED, norm1_b + i * EMBED, xln);
        // qkv
        gemm_k<false,false,false,false><<<dim3(9, 197, 1), 256>>>(
            xln, qkv_w + (long)i * EMBED * 3 * EMBED, qkv_b + i * 3 * EMBED,
            nullptr, nullptr, qkv, ROWS, 3 * EMBED, EMBED, 0, 0, 0);
        // split
        split_k<<<(int)(((long)ROWS * 576 + 255) / 256), 256>>>(qkv, q, k, v);
        // feature maps
        fmap_k<<<dim3(BATCH * HEADS * NTOK, 2), 256>>>(
            q, k, proj_mat + (long)i * FEAT * HDIM, pq, pk);
        // k cumsum + D_inv
        ksum_k<<<BATCH * HEADS, FEAT>>>(pk, ks);
        dinv_k<<<dim3(BATCH * HEADS, 25), 256>>>(pq, ks, dv);
        // attn = pq @ pk^T  (batched, TB)
        gemm_k<false,true,false,false><<<dim3(4, 4, BATCH * HEADS), 256>>>(
            pq, pk, nullptr, nullptr, nullptr, attn,
            NTOK, NTOK, FEAT, (long)NTOK * FEAT, (long)NTOK * FEAT, (long)NTOK * NTOK);
        // out = attn @ v, * D_inv, scatter to [B,N,EMBED]
        gemm_k<false,false,false,true><<<dim3(1, 4, BATCH * HEADS), 256>>>(
            attn, v, nullptr, nullptr, dv, ao,
            NTOK, HDIM, NTOK, (long)NTOK * NTOK, (long)NTOK * HDIM, 0);
        // attn proj + residual
        gemm_k<false,false,true,false><<<dim3(3, 197, 1), 256>>>(
            ao, attn_proj_w + (long)i * EMBED * EMBED, attn_proj_b + i * EMBED,
            h, nullptr, h, ROWS, EMBED, EMBED, 0, 0, 0);
        // LN2
        ln_k<<<ROWS, EMBED>>>(h, EMBED, norm2_w + i * EMBED, norm2_b + i * EMBED, xln);
        // MLP
        gemm_k<true,false,false,false><<<dim3(12, 197, 1), 256>>>(
            xln, fc1_w + (long)i * EMBED * MLPD, fc1_b + i * MLPD,
            nullptr, nullptr, mlp, ROWS, MLPD, EMBED, 0, 0, 0);
        gemm_k<false,false,true,false><<<dim3(3, 197, 1), 256>>>(
            mlp, fc2_w + (long)i * MLPD * EMBED, fc2_b + i * EMBED,
            h, nullptr, h, ROWS, EMBED, MLPD, 0, 0, 0);
        // early exits
        if (i == 3 || i == 7 || i == 11) {
            int e = (i == 3) ? 0 : (i == 7) ? 1 : 2;
            pool_k<<<BATCH, EMBED>>>(h, pool);
            gemm_k<false,false,false,false><<<dim3(16, 1, 1), 256>>>(
                pool, exit_w + (long)e * EMBED * NCLS, exit_b + e * NCLS,
                nullptr, nullptr, out + (long)(1 + e) * BATCH * NCLS,
                BATCH, NCLS, EMBED, 0, 0, 0);
        }
    }

    // final norm on cls token + head
    ln_k<<<BATCH, EMBED>>>(h, (long)NTOK * EMBED, final_norm_w, final_norm_b, cls);
    gemm_k<false,false,false,false><<<dim3(16, 1, 1), 256>>>(
        cls, head_w, head_b, nullptr, nullptr, out,
        BATCH, NCLS, EMBED, 0, 0, 0);
}

// round 2
// speedup vs baseline: 1.9426x; 1.9426x over previous
#include <cuda_runtime.h>
#include <math.h>

// ---------------- problem constants ----------------
#define BATCH 64
#define NTOK 197
#define NPATCH 196
#define EMBED 192
#define HEADS 3
#define HDIM 64
#define FEAT 256
#define MLPD 768
#define NCLS 1000
#define DEPTH 12
#define ROWS (BATCH*NTOK)          // 12608
#define BHN  (BATCH*HEADS*NTOK)    // 37824

// ---------------- scratch (device globals) ----------------
__device__ float g_h   [ROWS*EMBED];
__device__ float g_xln [ROWS*EMBED];
__device__ float g_qkv [ROWS*3*EMBED];
__device__ float g_qk  [2L*BHN*HDIM];     // [z=q|k][bh*NTOK+n][64]
__device__ float g_v   [BHN*HDIM];
__device__ float g_nrm [2L*BHN];          // row sq-norm / 2
__device__ float g_pqk [2L*BHN*FEAT];     // [z=pq|pk][bh*NTOK+n][256]
__device__ float g_ks  [BATCH*HEADS*FEAT];
__device__ float g_dv  [BATCH*HEADS*NTOK];
__device__ float g_kv  [BATCH*HEADS*FEAT*HDIM];
__device__ float g_ao  [ROWS*EMBED];
__device__ float g_mlp [ROWS*MLPD];
__device__ float g_pool[BATCH*EMBED];
__device__ float g_cls [BATCH*EMBED];

// ---------------- helpers ----------------
__device__ __forceinline__ float blockSum192(float v, float* sm) {
    #pragma unroll
    for (int o = 16; o > 0; o >>= 1) v += __shfl_down_sync(0xffffffffu, v, o);
    if ((threadIdx.x & 31) == 0) sm[threadIdx.x >> 5] = v;
    __syncthreads();
    float tot = 0.f;
    #pragma unroll
    for (int i = 0; i < 6; i++) tot += sm[i];
    __syncthreads();
    return tot;
}

#define FMA2(acc, a, b) asm("fma.rn.f32x2 %0, %1, %2, %0;" : "+l"(acc) : "l"(a), "l"(b))

// ---------------- FFMA2 register-tiled GEMM ----------------
// C[M,N] = op(A)[M,K] @ op(B)[K,N]   (batched over z)
// TA: A stored as [K, M] (row-major, row length = M)  -> computes A^T @ B
// TB: B stored as [N, K] (row-major)                  -> computes A @ B^T
// EPI: 0=bias, 1=bias+gelu, 2=bias+residual, 3=dinv-scale + head scatter,
//      4=exp(acc - aux[row]) * 64^-0.25
#define BM 128
#define BN 64
#define BK 16

template<int EPI, bool TA, bool TB>
__global__ __launch_bounds__(256)
void gemm2_k(const float* __restrict__ A, const float* __restrict__ Bm,
             const float* __restrict__ bias, const float* __restrict__ res,
             const float* __restrict__ aux, float* __restrict__ C,
             int M, int N, int K, long sA, long sB, long sC, long sAux)
{
    __shared__ __align__(16) float As [BK][BM + 4];
    __shared__ __align__(16) float BsD[BK][2*BN + 8];
    int z = blockIdx.z;
    const float* Ab = A + (long)z * sA;
    const float* Bb = Bm + (long)z * sB;
    int mBase = blockIdx.y * BM;
    int nBase = blockIdx.x * BN;
    int tid = threadIdx.x;
    int tx = tid & 15, ty = tid >> 4;

    unsigned long long acc[4][4];
    #pragma unroll
    for (int p = 0; p < 4; p++)
        #pragma unroll
        for (int j = 0; j < 4; j++) acc[p][j] = 0ULL;

    for (int k0 = 0; k0 < K; k0 += BK) {
        // ---- load A tile into As[kk][m] ----
        if (TA) {
            // A stored [K, M] row-major (row length M): coalesced along m
            #pragma unroll
            for (int u2 = 0; u2 < 2; u2++) {
                int linear = tid + u2 * 256;        // 512 slots: 16 kk x 32 m4
                int kk = linear >> 5;
                int m4 = (linear & 31) * 4;
                int gk = k0 + kk;
                #pragma unroll
                for (int u = 0; u < 4; u++) {
                    int gm = mBase + m4 + u;
                    As[kk][m4 + u] = (gk < K && gm < M)
                        ? Ab[(long)gk * M + gm] : 0.f;
                }
            }
        } else {
            // A stored [M, K] row-major
            #pragma unroll
            for (int u2 = 0; u2 < 2; u2++) {
                int linear = tid + u2 * 256;        // 512 slots: 128 m x 4 k4
                int m = linear >> 2;
                int k4 = (linear & 3) * 4;
                int gm = mBase + m;
                #pragma unroll
                for (int u = 0; u < 4; u++) {
                    int gk = k0 + k4 + u;
                    As[k4 + u][m] = (gm < M && gk < K)
                        ? Ab[(long)gm * K + gk] : 0.f;
                }
            }
        }
        // ---- load B tile DUPLICATED into BsD[kk][2n],[2n+1] ----
        if (TB) {
            int n  = tid >> 2;
            int k4 = (tid & 3) * 4;
            int gn = nBase + n;
            #pragma unroll
            for (int u = 0; u < 4; u++) {
                int gk = k0 + k4 + u;
                float v = (gn < N && gk < K) ? Bb[(long)gn * K + gk] : 0.f;
                BsD[k4 + u][2*n]   = v;
                BsD[k4 + u][2*n+1] = v;
            }
        } else {
            int kk = tid >> 4;
            int n4 = (tid & 15) * 4;
            int gk = k0 + kk;
            #pragma unroll
            for (int u = 0; u < 4; u++) {
                int gn = nBase + n4 + u;
                float v = (gk < K && gn < N) ? Bb[(long)gk * N + gn] : 0.f;
                BsD[kk][2*(n4+u)]   = v;
                BsD[kk][2*(n4+u)+1] = v;
            }
        }
        __syncthreads();
        // ---- FFMA2 mainloop ----
        #pragma unroll
        for (int kk = 0; kk < BK; kk++) {
            ulonglong2 a0 = *(const ulonglong2*)&As [kk][ty * 8];
            ulonglong2 a1 = *(const ulonglong2*)&As [kk][ty * 8 + 4];
            ulonglong2 b0 = *(const ulonglong2*)&BsD[kk][tx * 8];
            ulonglong2 b1 = *(const ulonglong2*)&BsD[kk][tx * 8 + 4];
            unsigned long long ap[4] = {a0.x, a0.y, a1.x, a1.y};
            unsigned long long bd[4] = {b0.x, b0.y, b1.x, b1.y};
            #pragma unroll
            for (int p = 0; p < 4; p++)
                #pragma unroll
                for (int j = 0; j < 4; j++)
                    FMA2(acc[p][j], ap[p], bd[j]);
        }
        __syncthreads();
    }

    // ---- epilogue ----
    union Cv { unsigned long long u; float2 f; };
    if (EPI == 3) {
        int bb = z / 3, hh = z % 3;
        float* Cp = C + (long)bb * NTOK * EMBED + hh * HDIM;
        #pragma unroll
        for (int p = 0; p < 4; p++) {
            int r0 = mBase + ty * 8 + p * 2;
            #pragma unroll
            for (int j = 0; j < 4; j++) {
                int col = nBase + tx * 4 + j;
                if (col >= N) continue;
                Cv cv; cv.u = acc[p][j];
                if (r0 < M)
                    Cp[(long)r0 * EMBED + col] = cv.f.x * aux[(long)z * NTOK + r0];
                if (r0 + 1 < M)
                    Cp[(long)(r0+1) * EMBED + col] = cv.f.y * aux[(long)z * NTOK + r0 + 1];
            }
        }
    } else {
        float* Cp = C + (long)z * sC;
        const float* auxz = aux ? aux + (long)z * sAux : nullptr;
        #pragma unroll
        for (int p = 0; p < 4; p++) {
            int r0 = mBase + ty * 8 + p * 2;
            #pragma unroll
            for (int j = 0; j < 4; j++) {
                int col = nBase + tx * 4 + j;
                if (col >= N) continue;
                Cv cv; cv.u = acc[p][j];
                float bv = bias ? bias[col] : 0.f;
                #pragma unroll
                for (int e = 0; e < 2; e++) {
                    int row = r0 + e;
                    if (row >= M) continue;
                    float vv = (e ? cv.f.y : cv.f.x);
                    if (EPI == 4) {
                        vv = __expf(vv - auxz[row]) * 0.35355339059327373f;
                    } else {
                        vv += bv;
                        if (EPI == 1) vv = 0.5f * vv * (1.0f + erff(vv * 0.70710678118654752f));
                        if (EPI == 2) vv += res[(long)row * N + col];
                    }
                    Cp[(long)row * N + col] = vv;
                }
            }
        }
    }
}

// ---------------- LayerNorm ----------------
__global__ void ln_k(const float* __restrict__ in, long rowStride,
                     const float* __restrict__ w, const float* __restrict__ b,
                     float* __restrict__ out)
{
    __shared__ float sm[8];
    long r = blockIdx.x;
    int t = threadIdx.x;
    float v = in[r * rowStride + t];
    float mu = blockSum192(v, sm) * (1.f / EMBED);
    float d = v - mu;
    float var = blockSum192(d * d, sm) * (1.f / EMBED);
    out[r * EMBED + t] = d * rsqrtf(var + 1e-5f) * w[t] + b[t];
}

// ---------------- patch embed + LN + pos ----------------
__global__ __launch_bounds__(192)
void patch_k(const float* __restrict__ x, const float* __restrict__ w,
             const float* __restrict__ wb, const float* __restrict__ lw,
             const float* __restrict__ lb, const float* __restrict__ pos,
             float* __restrict__ h)
{
    __shared__ float px[8][768];
    __shared__ float sm[8];
    int b = blockIdx.x;
    int pbase = blockIdx.y * 8;
    int np = NPATCH - pbase; if (np > 8) np = 8;
    int tid = threadIdx.x;

    for (int j = 0; j < np; j++) {
        int p = pbase + j;
        int gy = p / 14, gx = p % 14;
        for (int t = tid; t < 768; t += 192) {
            int c = t >> 8; int rem = t & 255; int r = rem >> 4; int col = rem & 15;
            px[j][t] = x[(((long)b * 3 + c) * 224 + gy * 16 + r) * 224 + gx * 16 + col];
        }
    }
    __syncthreads();

    float acc[8];
    #pragma unroll
    for (int j = 0; j < 8; j++) acc[j] = 0.f;
    const float4* wr = (const float4*)(w + (long)tid * 768);
    for (int k4 = 0; k4 < 192; k4++) {
        float4 wv = wr[k4];
        int k = k4 * 4;
        #pragma unroll
        for (int j = 0; j < 8; j++) {
            acc[j] += wv.x * px[j][k]   + wv.y * px[j][k+1]
                    + wv.z * px[j][k+2] + wv.w * px[j][k+3];
        }
    }
    float bval = wb[tid];
    for (int j = 0; j < np; j++) {
        float v = acc[j] + bval;
        float mu  = blockSum192(v, sm) * (1.f / 192.f);
        float d = v - mu;
        float var = blockSum192(d * d, sm) * (1.f / 192.f);
        float o = d * rsqrtf(var + 1e-5f) * lw[tid] + lb[tid];
        int p = pbase + j;
        h[((long)b * NTOK + 1 + p) * EMBED + tid] = o + pos[(1 + p) * EMBED + tid];
    }
}

__global__ void cls_k(const float* __restrict__ cls, const float* __restrict__ pos,
                      float* __restrict__ h)
{
    int b = blockIdx.x; int e = threadIdx.x;
    h[(long)b * NTOK * EMBED + e] = cls[e] + pos[e];
}

// ---------------- qkv split + per-head sq-norm/2 ----------------
__global__ __launch_bounds__(192)
void split_k(const float* __restrict__ qkv, float* __restrict__ qk,
             float* __restrict__ v, float* __restrict__ nrm)
{
    __shared__ float smq[6], smk[6];
    int row = blockIdx.x;           // b*NTOK + n
    int b = row / NTOK, n = row % NTOK;
    int t = threadIdx.x;
    int h = t >> 6, d = t & 63;
    long base = (long)row * 576;
    float qv = qkv[base + h * 64 + d];
    float kv = qkv[base + 192 + h * 64 + d];
    float vv = qkv[base + 384 + h * 64 + d];
    long o = (((long)b * 3 + h) * NTOK + n) * 64 + d;
    qk[o] = qv;
    qk[(long)BHN * HDIM + o] = kv;
    v[o] = vv;
    float sq = qv * qv, sk = kv * kv;
    #pragma unroll
    for (int off = 16; off > 0; off >>= 1) {
        sq += __shfl_down_sync(0xffffffffu, sq, off);
        sk += __shfl_down_sync(0xffffffffu, sk, off);
    }
    int wid = t >> 5;
    if ((t & 31) == 0) { smq[wid] = sq; smk[wid] = sk; }
    __syncthreads();
    if (t < 3) {
        long r = ((long)b * 3 + t) * NTOK + n;
        nrm[r]       = (smq[2*t] + smq[2*t+1]) * 0.5f;
        nrm[BHN + r] = (smk[2*t] + smk[2*t+1]) * 0.5f;
    }
}

// ---------------- k_cumsum over tokens ----------------
__global__ void ksum_k(const float* __restrict__ pk, float* __restrict__ ks)
{
    int z = blockIdx.x; int f = threadIdx.x;
    float s = 0.f;
    for (int n = 0; n < NTOK; n++) s += pk[((long)z * NTOK + n) * FEAT + f];
    ks[(long)z * FEAT + f] = s;
}

// ---------------- D_inv ----------------
__global__ __launch_bounds__(256)
void dinv_k(const float* __restrict__ pq, const float* __restrict__ ks,
            float* __restrict__ dv)
{
    __shared__ float s[FEAT];
    int z = blockIdx.x;
    int tid = threadIdx.x;
    s[tid] = ks[(long)z * FEAT + tid];
    __syncthreads();
    int w = tid >> 5, l = tid & 31;
    int n = blockIdx.y * 8 + w;
    if (n < NTOK) {
        const float* p = pq + ((long)z * NTOK + n) * FEAT;
        float acc = 0.f;
        #pragma unroll
        for (int f = 0; f < FEAT / 32; f++) acc += p[l + f * 32] * s[l + f * 32];
        #pragma unroll
        for (int o = 16; o > 0; o >>= 1) acc += __shfl_down_sync(0xffffffffu, acc, o);
        if (l == 0) dv[(long)z * NTOK + n] = 1.f / acc;
    }
}

// ---------------- token mean pool ----------------
__global__ void pool_k(const float* __restrict__ h, float* __restrict__ pool)
{
    int b = blockIdx.x; int e = threadIdx.x;
    float s = 0.f;
    for (int n = 0; n < NTOK; n++) s += h[((long)b * NTOK + n) * EMBED + e];
    pool[b * EMBED + e] = s * (1.f / 197.f);
}

// ---------------- host launch ----------------
extern "C" void kernel_launch(void* const* d_in, const int* in_sizes, int n_in,
                              void* d_out, int out_size)
{
    const float* x            = (const float*)d_in[0];
    const float* patch_w      = (const float*)d_in[1];
    const float* patch_b      = (const float*)d_in[2];
    const float* pe_norm_w    = (const float*)d_in[3];
    const float* pe_norm_b    = (const float*)d_in[4];
    const float* cls_token    = (const float*)d_in[5];
    const float* pos_embed    = (const float*)d_in[6];
    const float* norm1_w      = (const float*)d_in[7];
    const float* norm1_b      = (const float*)d_in[8];
    const float* qkv_w        = (const float*)d_in[9];
    const float* qkv_b        = (const float*)d_in[10];
    const float* proj_mat     = (const float*)d_in[11];
    const float* attn_proj_w  = (const float*)d_in[12];
    const float* attn_proj_b  = (const float*)d_in[13];
    const float* norm2_w      = (const float*)d_in[14];
    const float* norm2_b      = (const float*)d_in[15];
    const float* fc1_w        = (const float*)d_in[16];
    const float* fc1_b        = (const float*)d_in[17];
    const float* fc2_w        = (const float*)d_in[18];
    const float* fc2_b        = (const float*)d_in[19];
    const float* exit_w       = (const float*)d_in[20];
    const float* exit_b       = (const float*)d_in[21];
    const float* final_norm_w = (const float*)d_in[22];
    const float* final_norm_b = (const float*)d_in[23];
    const float* head_w       = (const float*)d_in[24];
    const float* head_b       = (const float*)d_in[25];
    float* out = (float*)d_out;

    float *h, *xln, *qkv, *qk, *v, *nrm, *pqk, *ks, *dv, *kv, *ao, *mlp, *pool, *cls;
    cudaGetSymbolAddress((void**)&h,    g_h);
    cudaGetSymbolAddress((void**)&xln,  g_xln);
    cudaGetSymbolAddress((void**)&qkv,  g_qkv);
    cudaGetSymbolAddress((void**)&qk,   g_qk);
    cudaGetSymbolAddress((void**)&v,    g_v);
    cudaGetSymbolAddress((void**)&nrm,  g_nrm);
    cudaGetSymbolAddress((void**)&pqk,  g_pqk);
    cudaGetSymbolAddress((void**)&ks,   g_ks);
    cudaGetSymbolAddress((void**)&dv,   g_dv);
    cudaGetSymbolAddress((void**)&kv,   g_kv);
    cudaGetSymbolAddress((void**)&ao,   g_ao);
    cudaGetSymbolAddress((void**)&mlp,  g_mlp);
    cudaGetSymbolAddress((void**)&pool, g_pool);
    cudaGetSymbolAddress((void**)&cls,  g_cls);

    const float* pk = pqk + (long)BHN * FEAT;

    // embed
    cls_k<<<BATCH, EMBED>>>(cls_token, pos_embed, h);
    patch_k<<<dim3(BATCH, 25), 192>>>(x, patch_w, patch_b, pe_norm_w, pe_norm_b,
                                      pos_embed, h);

    for (int i = 0; i < DEPTH; i++) {
        // LN1
        ln_k<<<ROWS, EMBED>>>(h, EMBED, norm1_w + i * EMBED, norm1_b + i * EMBED, xln);
        // qkv = xln @ Wqkv + b
        gemm2_k<0,false,false><<<dim3(9, 99, 1), 256>>>(
            xln, qkv_w + (long)i * EMBED * 3 * EMBED, qkv_b + i * 3 * EMBED,
            nullptr, nullptr, qkv, ROWS, 3 * EMBED, EMBED, 0, 0, 0, 0);
        // split into heads + sq-norms
        split_k<<<ROWS, 192>>>(qkv, qk, v, nrm);
        // feature maps: pqk[z] = exp(qk[z] @ pm^T - nrm[z]) * 64^-0.25
        gemm2_k<4,false,true><<<dim3(4, 296, 2), 256>>>(
            qk, proj_mat + (long)i * FEAT * HDIM, nullptr, nullptr, nrm, pqk,
            BHN, FEAT, HDIM, (long)BHN * HDIM, 0, (long)BHN * FEAT, (long)BHN);
        // k cumsum + D_inv
        ksum_k<<<BATCH * HEADS, FEAT>>>(pk, ks);
        dinv_k<<<dim3(BATCH * HEADS, 25), 256>>>(pqk, ks, dv);
        // kv = pk^T @ v   [z: 256 x 64], K = 197
        gemm2_k<0,true,false><<<dim3(1, 2, BATCH * HEADS), 256>>>(
            pk, v, nullptr, nullptr, nullptr, kv,
            FEAT, HDIM, NTOK, (long)NTOK * FEAT, (long)NTOK * HDIM,
            (long)FEAT * HDIM, 0);
        // ao = (pq @ kv) * D_inv, scattered to [B,N,EMBED]
        gemm2_k<3,false,false><<<dim3(1, 2, BATCH * HEADS), 256>>>(
            pqk, kv, nullptr, nullptr, dv, ao,
            NTOK, HDIM, FEAT, (long)NTOK * FEAT, (long)FEAT * HDIM, 0, 0);
        // attn proj + residual
        gemm2_k<2,false,false><<<dim3(3, 99, 1), 256>>>(
            ao, attn_proj_w + (long)i * EMBED * EMBED, attn_proj_b + i * EMBED,
            h, nullptr, h, ROWS, EMBED, EMBED, 0, 0, 0, 0);
        // LN2
        ln_k<<<ROWS, EMBED>>>(h, EMBED, norm2_w + i * EMBED, norm2_b + i * EMBED, xln);
        // MLP
        gemm2_k<1,false,false><<<dim3(12, 99, 1), 256>>>(
            xln, fc1_w + (long)i * EMBED * MLPD, fc1_b + i * MLPD,
            nullptr, nullptr, mlp, ROWS, MLPD, EMBED, 0, 0, 0, 0);
        gemm2_k<2,false,false><<<dim3(3, 99, 1), 256>>>(
            mlp, fc2_w + (long)i * MLPD * EMBED, fc2_b + i * EMBED,
            h, nullptr, h, ROWS, EMBED, MLPD, 0, 0, 0, 0);
        // early exits
        if (i == 3 || i == 7 || i == 11) {
            int e = (i == 3) ? 0 : (i == 7) ? 1 : 2;
            pool_k<<<BATCH, EMBED>>>(h, pool);
            gemm2_k<0,false,false><<<dim3(16, 1, 1), 256>>>(
                pool, exit_w + (long)e * EMBED * NCLS, exit_b + e * NCLS,
                nullptr, nullptr, out + (long)(1 + e) * BATCH * NCLS,
                BATCH, NCLS, EMBED, 0, 0, 0, 0);
        }
    }

    // final norm on cls token + head
    ln_k<<<BATCH, EMBED>>>(h, (long)NTOK * EMBED, final_norm_w, final_norm_b, cls);
    gemm2_k<0,false,false><<<dim3(16, 1, 1), 256>>>(
        cls, head_w, head_b, nullptr, nullptr, out,
        BATCH, NCLS, EMBED, 0, 0, 0, 0);
}

// round 3
// speedup vs baseline: 2.9364x; 1.5116x over previous
#include <cuda_runtime.h>
#include <math.h>

// ---------------- problem constants ----------------
#define BATCH 64
#define NTOK 197
#define NPATCH 196
#define EMBED 192
#define HEADS 3
#define HDIM 64
#define FEAT 256
#define MLPD 768
#define NCLS 1000
#define DEPTH 12
#define ROWS (BATCH*NTOK)          // 12608
#define BHN  (BATCH*HEADS*NTOK)    // 37824

// ---------------- scratch (device globals) ----------------
__device__ float g_h   [ROWS*EMBED];
__device__ float g_xln [ROWS*EMBED];
__device__ float g_qkv [ROWS*3*EMBED];
__device__ float g_qk  [2L*BHN*HDIM];
__device__ float g_v   [BHN*HDIM];
__device__ float g_nrm [2L*BHN];
__device__ float g_pqk [2L*BHN*FEAT];
__device__ float g_ks  [BATCH*HEADS*FEAT];
__device__ float g_dv  [BATCH*HEADS*NTOK];
__device__ float g_kv  [BATCH*HEADS*FEAT*HDIM];
__device__ float g_ao  [ROWS*EMBED];      // also tok buffer for patch embed
__device__ float g_mlp [ROWS*MLPD];       // also im2col buffer
__device__ float g_pool[BATCH*EMBED];
__device__ float g_cls [BATCH*EMBED];

// ---------------- helpers ----------------
__device__ __forceinline__ float blockSum192(float v, float* sm) {
    #pragma unroll
    for (int o = 16; o > 0; o >>= 1) v += __shfl_down_sync(0xffffffffu, v, o);
    if ((threadIdx.x & 31) == 0) sm[threadIdx.x >> 5] = v;
    __syncthreads();
    float tot = 0.f;
    #pragma unroll
    for (int i = 0; i < 6; i++) tot += sm[i];
    __syncthreads();
    return tot;
}

#define FMA2(acc, a, b) asm("fma.rn.f32x2 %0, %1, %2, %0;" : "+l"(acc) : "l"(a), "l"(b))
#define PACK2(dst, s)   asm("mov.b64 %0, {%1, %1};" : "=l"(dst) : "f"(s))

// ---------------- FFMA2 GEMM, pairs along N, A dup in registers ----------------
// C[M,N] = op(A)[M,K] @ op(B)[K,N]   (batched over z)
// TA: A stored [K,M] row-major -> A^T @ B.   TB: B stored [N,K] -> A @ B^T.
// EPI: 0=bias, 1=bias+gelu, 2=bias+residual,
//      3=dinv-scale + head scatter, 4=exp(acc - aux[row]) * 64^-0.25
#define BKq 16

template<int EPI, bool TA, bool TB, int BMv, int BNv>
__global__ __launch_bounds__((BMv/8)*(BNv/8), 2)
void gemm3_k(const float* __restrict__ A, const float* __restrict__ Bm,
             const float* __restrict__ bias, const float* __restrict__ res,
             const float* __restrict__ aux, float* __restrict__ C,
             int M, int N, int K, long sA, long sB, long sC, long sAux)
{
    constexpr int THREADS = (BMv/8)*(BNv/8);
    constexpr int CT = BNv/8;
    __shared__ __align__(16) float As[2][BKq][BMv + 4];
    __shared__ __align__(16) float Bs[2][BKq][BNv + 4];

    int z = blockIdx.z;
    const float* Ab = A + (long)z * sA;
    const float* Bb = Bm + (long)z * sB;
    int mBase = blockIdx.y * BMv;
    int nBase = blockIdx.x * BNv;
    int tid = threadIdx.x;
    int rt = tid / CT, ct = tid % CT;

    unsigned long long acc[8][4];
    #pragma unroll
    for (int i = 0; i < 8; i++)
        #pragma unroll
        for (int j = 0; j < 4; j++) acc[i][j] = 0ULL;

    // ---- tile loader ----
    auto loadTile = [&](int buf, int k0) {
        // A tile
        if (TA) {
            constexpr int F = 4 * BMv / THREADS;
            #pragma unroll
            for (int f = 0; f < F; f++) {
                int l = tid + f * THREADS;
                int kk = l / (BMv / 4);
                int m4 = (l % (BMv / 4)) * 4;
                int gk = k0 + kk;
                float4 v = make_float4(0.f, 0.f, 0.f, 0.f);
                if (gk < K) {
                    if (mBase + m4 + 3 < M) {
                        v = *(const float4*)(Ab + (long)gk * M + mBase + m4);
                    } else {
                        float t[4];
                        #pragma unroll
                        for (int u = 0; u < 4; u++)
                            t[u] = (mBase + m4 + u < M) ? Ab[(long)gk * M + mBase + m4 + u] : 0.f;
                        v = make_float4(t[0], t[1], t[2], t[3]);
                    }
                }
                *(float4*)&As[buf][kk][m4] = v;
            }
        } else {
            constexpr int F = 4 * BMv / THREADS;
            #pragma unroll
            for (int f = 0; f < F; f++) {
                int l = tid + f * THREADS;
                int m = l >> 2, k4 = (l & 3) * 4;
                int gm = mBase + m;
                float4 v = make_float4(0.f, 0.f, 0.f, 0.f);
                if (gm < M) {
                    if (k0 + k4 + 3 < K) {
                        v = *(const float4*)(Ab + (long)gm * K + k0 + k4);
                    } else {
                        float t[4];
                        #pragma unroll
                        for (int u = 0; u < 4; u++)
                            t[u] = (k0 + k4 + u < K) ? Ab[(long)gm * K + k0 + k4 + u] : 0.f;
                        v = make_float4(t[0], t[1], t[2], t[3]);
                    }
                }
                As[buf][k4 + 0][m] = v.x;
                As[buf][k4 + 1][m] = v.y;
                As[buf][k4 + 2][m] = v.z;
                As[buf][k4 + 3][m] = v.w;
            }
        }
        // B tile
        if (TB) {
            constexpr int F = 4 * BNv / THREADS;
            #pragma unroll
            for (int f = 0; f < F; f++) {
                int l = tid + f * THREADS;
                int n = l >> 2, k4 = (l & 3) * 4;
                int gn = nBase + n;
                float4 v = make_float4(0.f, 0.f, 0.f, 0.f);
                if (gn < N) {
                    if (k0 + k4 + 3 < K) {
                        v = *(const float4*)(Bb + (long)gn * K + k0 + k4);
                    } else {
                        float t[4];
                        #pragma unroll
                        for (int u = 0; u < 4; u++)
                            t[u] = (k0 + k4 + u < K) ? Bb[(long)gn * K + k0 + k4 + u] : 0.f;
                        v = make_float4(t[0], t[1], t[2], t[3]);
                    }
                }
                Bs[buf][k4 + 0][n] = v.x;
                Bs[buf][k4 + 1][n] = v.y;
                Bs[buf][k4 + 2][n] = v.z;
                Bs[buf][k4 + 3][n] = v.w;
            }
        } else {
            constexpr int F = 4 * BNv / THREADS;
            #pragma unroll
            for (int f = 0; f < F; f++) {
                int l = tid + f * THREADS;
                int kk = l / (BNv / 4);
                int n4 = (l % (BNv / 4)) * 4;
                int gk = k0 + kk;
                float4 v = make_float4(0.f, 0.f, 0.f, 0.f);
                if (gk < K) {
                    if (nBase + n4 + 3 < N) {
                        v = *(const float4*)(Bb + (long)gk * N + nBase + n4);
                    } else {
                        float t[4];
                        #pragma unroll
                        for (int u = 0; u < 4; u++)
                            t[u] = (nBase + n4 + u < N) ? Bb[(long)gk * N + nBase + n4 + u] : 0.f;
                        v = make_float4(t[0], t[1], t[2], t[3]);
                    }
                }
                *(float4*)&Bs[buf][kk][n4] = v;
            }
        }
    };

    int buf = 0;
    loadTile(0, 0);
    __syncthreads();

    for (int k0 = 0; k0 < K; k0 += BKq) {
        if (k0 + BKq < K) loadTile(buf ^ 1, k0 + BKq);
        #pragma unroll
        for (int kk = 0; kk < BKq; kk++) {
            float4 a0 = *(const float4*)&As[buf][kk][rt * 8];
            float4 a1 = *(const float4*)&As[buf][kk][rt * 8 + 4];
            ulonglong2 b0 = *(const ulonglong2*)&Bs[buf][kk][ct * 8];
            ulonglong2 b1 = *(const ulonglong2*)&Bs[buf][kk][ct * 8 + 4];
            unsigned long long bp[4] = {b0.x, b0.y, b1.x, b1.y};
            float av[8] = {a0.x, a0.y, a0.z, a0.w, a1.x, a1.y, a1.z, a1.w};
            unsigned long long ap[8];
            #pragma unroll
            for (int i = 0; i < 8; i++) PACK2(ap[i], av[i]);
            #pragma unroll
            for (int i = 0; i < 8; i++)
                #pragma unroll
                for (int j = 0; j < 4; j++)
                    FMA2(acc[i][j], ap[i], bp[j]);
        }
        __syncthreads();
        buf ^= 1;
    }

    // ---- epilogue ----
    union F2 { unsigned long long u; float2 f; };
    if (EPI == 3) {
        int bb = z / 3, hh = z % 3;
        float* Cp = C + (long)bb * NTOK * EMBED + hh * HDIM;
        #pragma unroll
        for (int i = 0; i < 8; i++) {
            int row = mBase + rt * 8 + i;
            if (row >= M) continue;
            float dvv = aux[(long)z * NTOK + row];
            #pragma unroll
            for (int j = 0; j < 4; j++) {
                int cb = nBase + ct * 8 + 2 * j;
                if (cb >= N) continue;
                F2 t; t.u = acc[i][j];
                t.f.x *= dvv; t.f.y *= dvv;
                *(float2*)&Cp[(long)row * EMBED + cb] = t.f;
            }
        }
    } else {
        float* Cp = C + (long)z * sC;
        const float* auxz = aux ? aux + (long)z * sAux : nullptr;
        #pragma unroll
        for (int i = 0; i < 8; i++) {
            int row = mBase + rt * 8 + i;
            if (row >= M) continue;
            #pragma unroll
            for (int j = 0; j < 4; j++) {
                int cb = nBase + ct * 8 + 2 * j;
                if (cb >= N) continue;
                F2 t; t.u = acc[i][j];
                if (EPI == 4) {
                    float nr = auxz[row];
                    t.f.x = __expf(t.f.x - nr) * 0.35355339059327373f;
                    t.f.y = __expf(t.f.y - nr) * 0.35355339059327373f;
                } else {
                    if (bias) { t.f.x += bias[cb]; t.f.y += bias[cb + 1]; }
                    if (EPI == 1) {
                        t.f.x = 0.5f * t.f.x * (1.0f + erff(t.f.x * 0.70710678118654752f));
                        t.f.y = 0.5f * t.f.y * (1.0f + erff(t.f.y * 0.70710678118654752f));
                    }
                    if (EPI == 2) {
                        float2 r = *(const float2*)&res[(long)row * N + cb];
                        t.f.x += r.x; t.f.y += r.y;
                    }
                }
                *(float2*)&Cp[(long)row * N + cb] = t.f;
            }
        }
    }
}

// ---------------- LayerNorm ----------------
__global__ void ln_k(const float* __restrict__ in, long rowStride,
                     const float* __restrict__ w, const float* __restrict__ b,
                     float* __restrict__ out)
{
    __shared__ float sm[8];
    long r = blockIdx.x;
    int t = threadIdx.x;
    float v = in[r * rowStride + t];
    float mu = blockSum192(v, sm) * (1.f / EMBED);
    float d = v - mu;
    float var = blockSum192(d * d, sm) * (1.f / EMBED);
    out[r * EMBED + t] = d * rsqrtf(var + 1e-5f) * w[t] + b[t];
}

// ---------------- im2col for patch embed ----------------
__global__ void im2col_k(const float* __restrict__ x, float* __restrict__ px)
{
    long idx = (long)blockIdx.x * 256 + threadIdx.x;
    if (idx >= (long)NPATCH * BATCH * 768) return;
    int t = (int)(idx % 768);
    long rp = idx / 768;               // b*196 + p
    int b = (int)(rp / NPATCH), p = (int)(rp % NPATCH);
    int c = t >> 8, rem = t & 255, r = rem >> 4, col = rem & 15;
    int gy = p / 14, gx = p % 14;
    px[idx] = x[(((long)b * 3 + c) * 224 + gy * 16 + r) * 224 + gx * 16 + col];
}

// ---------------- patch LN + pos embed ----------------
__global__ void lnpos_k(const float* __restrict__ tok, const float* __restrict__ w,
                        const float* __restrict__ b, const float* __restrict__ pos,
                        float* __restrict__ h)
{
    __shared__ float sm[8];
    int r = blockIdx.x;                // b*196 + p
    int bb = r / NPATCH, p = r % NPATCH;
    int t = threadIdx.x;
    float v = tok[(long)r * EMBED + t];
    float mu = blockSum192(v, sm) * (1.f / EMBED);
    float d = v - mu;
    float var = blockSum192(d * d, sm) * (1.f / EMBED);
    float o = d * rsqrtf(var + 1e-5f) * w[t] + b[t];
    h[((long)bb * NTOK + 1 + p) * EMBED + t] = o + pos[(1 + p) * EMBED + t];
}

__global__ void cls_k(const float* __restrict__ cls, const float* __restrict__ pos,
                      float* __restrict__ h)
{
    int b = blockIdx.x; int e = threadIdx.x;
    h[(long)b * NTOK * EMBED + e] = cls[e] + pos[e];
}

// ---------------- qkv split + per-head sq-norm/2 ----------------
__global__ __launch_bounds__(192)
void split_k(const float* __restrict__ qkv, float* __restrict__ qk,
             float* __restrict__ v, float* __restrict__ nrm)
{
    __shared__ float smq[6], smk[6];
    int row = blockIdx.x;
    int b = row / NTOK, n = row % NTOK;
    int t = threadIdx.x;
    int h = t >> 6, d = t & 63;
    long base = (long)row * 576;
    float qv = qkv[base + h * 64 + d];
    float kv = qkv[base + 192 + h * 64 + d];
    float vv = qkv[base + 384 + h * 64 + d];
    long o = (((long)b * 3 + h) * NTOK + n) * 64 + d;
    qk[o] = qv;
    qk[(long)BHN * HDIM + o] = kv;
    v[o] = vv;
    float sq = qv * qv, sk = kv * kv;
    #pragma unroll
    for (int off = 16; off > 0; off >>= 1) {
        sq += __shfl_down_sync(0xffffffffu, sq, off);
        sk += __shfl_down_sync(0xffffffffu, sk, off);
    }
    int wid = t >> 5;
    if ((t & 31) == 0) { smq[wid] = sq; smk[wid] = sk; }
    __syncthreads();
    if (t < 3) {
        long r = ((long)b * 3 + t) * NTOK + n;
        nrm[r]       = (smq[2*t] + smq[2*t+1]) * 0.5f;
        nrm[BHN + r] = (smk[2*t] + smk[2*t+1]) * 0.5f;
    }
}

// ---------------- k_cumsum ----------------
__global__ void ksum_k(const float* __restrict__ pk, float* __restrict__ ks)
{
    int z = blockIdx.x; int f = threadIdx.x;
    float s = 0.f;
    for (int n = 0; n < NTOK; n++) s += pk[((long)z * NTOK + n) * FEAT + f];
    ks[(long)z * FEAT + f] = s;
}

// ---------------- D_inv ----------------
__global__ __launch_bounds__(256)
void dinv_k(const float* __restrict__ pq, const float* __restrict__ ks,
            float* __restrict__ dv)
{
    __shared__ float s[FEAT];
    int z = blockIdx.x;
    int tid = threadIdx.x;
    s[tid] = ks[(long)z * FEAT + tid];
    __syncthreads();
    int w = tid >> 5, l = tid & 31;
    int n = blockIdx.y * 8 + w;
    if (n < NTOK) {
        const float* p = pq + ((long)z * NTOK + n) * FEAT;
        float acc = 0.f;
        #pragma unroll
        for (int f = 0; f < FEAT / 32; f++) acc += p[l + f * 32] * s[l + f * 32];
        #pragma unroll
        for (int o = 16; o > 0; o >>= 1) acc += __shfl_down_sync(0xffffffffu, acc, o);
        if (l == 0) dv[(long)z * NTOK + n] = 1.f / acc;
    }
}

// ---------------- token mean pool ----------------
__global__ void pool_k(const float* __restrict__ h, float* __restrict__ pool)
{
    int b = blockIdx.x; int e = threadIdx.x;
    float s = 0.f;
    for (int n = 0; n < NTOK; n++) s += h[((long)b * NTOK + n) * EMBED + e];
    pool[b * EMBED + e] = s * (1.f / 197.f);
}

// ---------------- host launch ----------------
extern "C" void kernel_launch(void* const* d_in, const int* in_sizes, int n_in,
                              void* d_out, int out_size)
{
    const float* x            = (const float*)d_in[0];
    const float* patch_w      = (const float*)d_in[1];
    const float* patch_b      = (const float*)d_in[2];
    const float* pe_norm_w    = (const float*)d_in[3];
    const float* pe_norm_b    = (const float*)d_in[4];
    const float* cls_token    = (const float*)d_in[5];
    const float* pos_embed    = (const float*)d_in[6];
    const float* norm1_w      = (const float*)d_in[7];
    const float* norm1_b      = (const float*)d_in[8];
    const float* qkv_w        = (const float*)d_in[9];
    const float* qkv_b        = (const float*)d_in[10];
    const float* proj_mat     = (const float*)d_in[11];
    const float* attn_proj_w  = (const float*)d_in[12];
    const float* attn_proj_b  = (const float*)d_in[13];
    const float* norm2_w      = (const float*)d_in[14];
    const float* norm2_b      = (const float*)d_in[15];
    const float* fc1_w        = (const float*)d_in[16];
    const float* fc1_b        = (const float*)d_in[17];
    const float* fc2_w        = (const float*)d_in[18];
    const float* fc2_b        = (const float*)d_in[19];
    const float* exit_w       = (const float*)d_in[20];
    const float* exit_b       = (const float*)d_in[21];
    const float* final_norm_w = (const float*)d_in[22];
    const float* final_norm_b = (const float*)d_in[23];
    const float* head_w       = (const float*)d_in[24];
    const float* head_b       = (const float*)d_in[25];
    float* out = (float*)d_out;

    float *h, *xln, *qkv, *qk, *v, *nrm, *pqk, *ks, *dv, *kv, *ao, *mlp, *pool, *cls;
    cudaGetSymbolAddress((void**)&h,    g_h);
    cudaGetSymbolAddress((void**)&xln,  g_xln);
    cudaGetSymbolAddress((void**)&qkv,  g_qkv);
    cudaGetSymbolAddress((void**)&qk,   g_qk);
    cudaGetSymbolAddress((void**)&v,    g_v);
    cudaGetSymbolAddress((void**)&nrm,  g_nrm);
    cudaGetSymbolAddress((void**)&pqk,  g_pqk);
    cudaGetSymbolAddress((void**)&ks,   g_ks);
    cudaGetSymbolAddress((void**)&dv,   g_dv);
    cudaGetSymbolAddress((void**)&kv,   g_kv);
    cudaGetSymbolAddress((void**)&ao,   g_ao);
    cudaGetSymbolAddress((void**)&mlp,  g_mlp);
    cudaGetSymbolAddress((void**)&pool, g_pool);
    cudaGetSymbolAddress((void**)&cls,  g_cls);

    const float* pk = pqk + (long)BHN * FEAT;

    // ---- patch embed: im2col -> GEMM -> LN+pos ----
    cls_k<<<BATCH, EMBED>>>(cls_token, pos_embed, h);
    im2col_k<<<(int)(((long)NPATCH * BATCH * 768 + 255) / 256), 256>>>(x, mlp);
    gemm3_k<0,false,true,128,64><<<dim3(3, 98, 1), 128>>>(
        mlp, patch_w, patch_b, nullptr, nullptr, ao,
        NPATCH * BATCH, EMBED, 768, 0, 0, 0, 0);
    lnpos_k<<<NPATCH * BATCH, EMBED>>>(ao, pe_norm_w, pe_norm_b, pos_embed, h);

    for (int i = 0; i < DEPTH; i++) {
        ln_k<<<ROWS, EMBED>>>(h, EMBED, norm1_w + i * EMBED, norm1_b + i * EMBED, xln);
        // qkv
        gemm3_k<0,false,false,128,128><<<dim3(5, 99, 1), 256>>>(
            xln, qkv_w + (long)i * EMBED * 3 * EMBED, qkv_b + i * 3 * EMBED,
            nullptr, nullptr, qkv, ROWS, 3 * EMBED, EMBED, 0, 0, 0, 0);
        split_k<<<ROWS, 192>>>(qkv, qk, v, nrm);
        // feature maps
        gemm3_k<4,false,true,128,128><<<dim3(2, 296, 2), 256>>>(
            qk, proj_mat + (long)i * FEAT * HDIM, nullptr, nullptr, nrm, pqk,
            BHN, FEAT, HDIM, (long)BHN * HDIM, 0, (long)BHN * FEAT, (long)BHN);
        ksum_k<<<BATCH * HEADS, FEAT>>>(pk, ks);
        dinv_k<<<dim3(BATCH * HEADS, 25), 256>>>(pqk, ks, dv);
        // kv = pk^T @ v
        gemm3_k<0,true,false,128,64><<<dim3(1, 2, BATCH * HEADS), 128>>>(
            pk, v, nullptr, nullptr, nullptr, kv,
            FEAT, HDIM, NTOK, (long)NTOK * FEAT, (long)NTOK * HDIM,
            (long)FEAT * HDIM, 0);
        // ao = (pq @ kv) * D_inv  (scatter to [B,N,EMBED])
        gemm3_k<3,false,false,128,64><<<dim3(1, 2, BATCH * HEADS), 128>>>(
            pqk, kv, nullptr, nullptr, dv, ao,
            NTOK, HDIM, FEAT, (long)NTOK * FEAT, (long)FEAT * HDIM, 0, 0);
        // attn proj + residual
        gemm3_k<2,false,false,128,64><<<dim3(3, 99, 1), 128>>>(
            ao, attn_proj_w + (long)i * EMBED * EMBED, attn_proj_b + i * EMBED,
            h, nullptr, h, ROWS, EMBED, EMBED, 0, 0, 0, 0);
        ln_k<<<ROWS, EMBED>>>(h, EMBED, norm2_w + i * EMBED, norm2_b + i * EMBED, xln);
        // MLP
        gemm3_k<1,false,false,128,128><<<dim3(6, 99, 1), 256>>>(
            xln, fc1_w + (long)i * EMBED * MLPD, fc1_b + i * MLPD,
            nullptr, nullptr, mlp, ROWS, MLPD, EMBED, 0, 0, 0, 0);
        gemm3_k<2,false,false,128,64><<<dim3(3, 99, 1), 128>>>(
            mlp, fc2_w + (long)i * MLPD * EMBED, fc2_b + i * EMBED,
            h, nullptr, h, ROWS, EMBED, MLPD, 0, 0, 0, 0);
        if (i == 3 || i == 7 || i == 11) {
            int e = (i == 3) ? 0 : (i == 7) ? 1 : 2;
            pool_k<<<BATCH, EMBED>>>(h, pool);
            gemm3_k<0,false,false,128,64><<<dim3(16, 1, 1), 128>>>(
                pool, exit_w + (long)e * EMBED * NCLS, exit_b + e * NCLS,
                nullptr, nullptr, out + (long)(1 + e) * BATCH * NCLS,
                BATCH, NCLS, EMBED, 0, 0, 0, 0);
        }
    }

    ln_k<<<BATCH, EMBED>>>(h, (long)NTOK * EMBED, final_norm_w, final_norm_b, cls);
    gemm3_k<0,false,false,128,64><<<dim3(16, 1, 1), 128>>>(
        cls, head_w, head_b, nullptr, nullptr, out,
        BATCH, NCLS, EMBED, 0, 0, 0, 0);
}